// round 5
// baseline (speedup 1.0000x reference)
#include <cuda_runtime.h>
#include <math.h>

#define BB 8
#define LL 1024
#define NT 10
#define SS 2.1972245773362196f   // log(9)

// ---- static device scratch (no allocation allowed) ----
__device__ float g_uu[BB*LL*LL];           // 32 MB
__device__ float g_ah[BB*LL*LL];           // 32 MB
__device__ float g_partial[2][BB*LL*32];   // double-buffered per-row partial sums
__device__ float g_lmbd[2][BB*LL];         // double-buffered lambda state

__device__ __forceinline__ float sigm(float v){ return 1.0f/(1.0f+__expf(-v)); }

__device__ __forceinline__ float wsum(float v){
  #pragma unroll
  for (int o=16;o;o>>=1) v += __shfl_xor_sync(0xffffffffu, v, o);
  return v;
}

__device__ __forceinline__ float mcalc(const float (&fR)[4][32], int r,
                                       const float (&fC)[4][32], int c){
  float bai=fR[0][r], bui=fR[1][r], bci=fR[2][r], bgi=fR[3][r];
  float baj=fC[0][c], buj=fC[1][c], bcj=fC[2][c], bgj=fC[3][c];
  return bai*buj + baj*bui + bci*bgj + bcj*bgi + bui*bgj + buj*bgi;
}

// m from row factors (shared) and column factors (registers)
__device__ __forceinline__ float mrc(const float (&fR)[4][32], int r,
                                     float aJ, float uJ, float cJ, float gJ){
  float ai=fR[0][r], ui=fR[1][r], ci=fR[2][r], gi=fR[3][r];
  return ai*uJ + aJ*ui + ci*gJ + cJ*gi + ui*gJ + uJ*gi;
}

// 3->3(relu)->1(relu) MLP; w layout: [0:9)=W1 (o*3+i), [9:12)=b1, [12:15)=W2, [15]=b2
__device__ __forceinline__ float mlp3(const float* w, float f0, float f1, float f2){
  float h0 = fmaxf(fmaf(w[0],f0,fmaf(w[1],f1,fmaf(w[2],f2,w[9]))),  0.f);
  float h1 = fmaxf(fmaf(w[3],f0,fmaf(w[4],f1,fmaf(w[5],f2,w[10]))), 0.f);
  float h2 = fmaxf(fmaf(w[6],f0,fmaf(w[7],f1,fmaf(w[8],f2,w[11]))), 0.f);
  return fmaxf(fmaf(w[12],h0,fmaf(w[13],h1,fmaf(w[14],h2,w[15]))), 0.f);
}

__device__ __forceinline__ void decode_pair(int p, int &I, int &J){
  I = (int)((sqrtf(8.f*(float)p+1.f)-1.f)*0.5f);
  while ((I+1)*(I+2)/2 <= p) ++I;
  while (I*(I+1)/2 > p) --I;
  J = p - I*(I+1)/2;
}

// ---------------- init: uu, a_hat, rowsum partials of a0 (into buf 0) ----------------
__global__ void __launch_bounds__(256)
init_kernel(const float* __restrict__ u, const float* __restrict__ x)
{
  int b = blockIdx.y;
  int I, J; decode_pair(blockIdx.x, I, J);
  bool diag = (I==J);
  int i0 = I*32, j0 = J*32;
  int tid = threadIdx.x, tx = tid&31, ty = tid>>5;

  __shared__ float sq1[32][33], sq2[32][33];
  __shared__ float fI[4][32], fJ[4][32];

  if (tid < 32) {
    float4 v = ((const float4*)x)[b*LL + i0 + tid];
    fI[0][tid]=v.x; fI[1][tid]=v.y; fI[2][tid]=v.z; fI[3][tid]=v.w;
  } else if (tid < 64) {
    int l = tid-32;
    float4 v = ((const float4*)x)[b*LL + j0 + l];
    fJ[0][l]=v.x; fJ[1][l]=v.y; fJ[2][l]=v.z; fJ[3][l]=v.w;
  }

  const size_t base = (size_t)b*LL*LL;
  #pragma unroll
  for (int k=0;k<4;k++){
    int r = ty + 8*k;
    size_t g1 = base + (size_t)(i0+r)*LL + j0 + tx;
    float uv = u[g1];
    float uu = sigm(2.f*(uv - SS))*uv;
    float ah = sigm(uu)*sigm(2.f*(uu - SS));
    g_uu[g1] = uu; g_ah[g1] = ah;
    sq1[r][tx] = ah*ah;
    if (!diag) {
      size_t g2 = base + (size_t)(j0+r)*LL + i0 + tx;
      float uv2 = u[g2];
      float uu2v = sigm(2.f*(uv2 - SS))*uv2;
      float ah2v = sigm(uu2v)*sigm(2.f*(uu2v - SS));
      g_uu[g2] = uu2v; g_ah[g2] = ah2v;
      sq2[r][tx] = ah2v*ah2v;
    }
  }
  __syncthreads();

  #pragma unroll
  for (int k=0;k<4;k++){
    int r = ty + 8*k;
    float sT = diag ? sq1[tx][r] : sq2[tx][r];
    float a1 = 0.5f*(sq1[r][tx] + sT) * mcalc(fI, r, fJ, tx);
    float rs1 = wsum(a1);
    if (tx==0) g_partial[0][(b*LL + i0 + r)*32 + J] = rs1;
    if (!diag){
      float a2 = 0.5f*(sq2[r][tx] + sq1[tx][r]) * mcalc(fJ, r, fI, tx);
      float rs2 = wsum(a2);
      if (tx==0) g_partial[0][(b*LL + j0 + r)*32 + I] = rs2;
    }
  }
}

// ---------------- main per-timestep kernel (lambda/s fused, 512 threads) ----------------
__global__ void __launch_bounds__(512,2)
step_kernel(const float* __restrict__ x,
  const float* __restrict__ aW1, const float* __restrict__ ab1,
  const float* __restrict__ aW2, const float* __restrict__ ab2,
  const float* __restrict__ rW1, const float* __restrict__ rb1,
  const float* __restrict__ rW2, const float* __restrict__ rb2,
  const float* __restrict__ lW1, const float* __restrict__ lb1,
  const float* __restrict__ lW2, const float* __restrict__ lb2,
  int t, float* __restrict__ out)   // out pre-offset to timestep slice
{
  int b = blockIdx.y;
  int I, J; decode_pair(blockIdx.x, I, J);
  bool diag = (I==J);
  int i0 = I*32, j0 = J*32;
  int tid = threadIdx.x, tx = tid&31, ty = tid>>5;   // ty 0..15

  __shared__ float uu1[32][33], uu2[32][33];
  __shared__ float sq1[32][33], sq2[32][33];
  __shared__ float fI[4][32], fJ[4][32];
  __shared__ float sI[32], sJ[32];
  __shared__ float wS[32];

  const int rdbuf = t & 1, wrbuf = (t+1) & 1;

  // -- setup: per-row factors, weight staging, fused lambda/s --
  if (tid < 32) {
    float4 v = ((const float4*)x)[b*LL + i0 + tid];
    fI[0][tid]=v.x; fI[1][tid]=v.y; fI[2][tid]=v.z; fI[3][tid]=v.w;
  } else if (tid < 64) {
    int l = tid-32;
    float4 v = ((const float4*)x)[b*LL + j0 + l];
    fJ[0][l]=v.x; fJ[1][l]=v.y; fJ[2][l]=v.z; fJ[3][l]=v.w;
  } else if (tid < 128) {
    // fused row work: rowsum -> lg -> lambda update -> s
    int q = tid - 64;
    int row = (q < 32) ? (i0 + q) : (j0 + (q - 32));
    int gi = b*LL + row;
    float rs = 0.f;
    const float4* pp = (const float4*)(&g_partial[rdbuf][(size_t)gi*32]);
    #pragma unroll
    for (int e=0;e<8;e++){ float4 v = pp[e]; rs += (v.x+v.y) + (v.z+v.w); }
    float lg = fmaxf(rs - 1.f, 0.f);
    float lm;
    if (t == 0) {
      lm = lg;                               // W_PEN = 1
    } else {
      float l0 = g_lmbd[rdbuf][gi];
      float h0 = fmaxf(fmaf(__ldg(lW1+0),l0,fmaf(__ldg(lW1+1),lg,__ldg(lb1+0))), 0.f);
      float h1 = fmaxf(fmaf(__ldg(lW1+2),l0,fmaf(__ldg(lW1+3),lg,__ldg(lb1+1))), 0.f);
      float h2 = fmaxf(fmaf(__ldg(lW1+4),l0,fmaf(__ldg(lW1+5),lg,__ldg(lb1+2))), 0.f);
      lm = fmaxf(fmaf(__ldg(lW2+0),h0,fmaf(__ldg(lW2+1),h1,fmaf(__ldg(lW2+2),h2,__ldg(lb2+0)))), 0.f);
    }
    g_lmbd[wrbuf][gi] = lm;                  // duplicate identical writes: deterministic
    float s = lm * sigm(2.f*(rs - 1.f));
    if (q < 32) sI[q] = s; else sJ[q-32] = s;
  } else if (tid < 144) {
    int l = tid-128;
    wS[l] = (l<9) ? aW1[l] : (l<12) ? ab1[l-9] : (l<15) ? aW2[l-12] : ab2[0];
  } else if (tid < 160) {
    int l = tid-144;
    wS[16+l] = (l<9) ? rW1[l] : (l<12) ? rb1[l-9] : (l<15) ? rW2[l-12] : rb2[0];
  }

  // -- load tiles (all 512 threads; 2 rows per tile per thread) --
  float ah1[2], ah2[2];
  const size_t base = (size_t)b*LL*LL;
  #pragma unroll
  for (int k=0;k<2;k++){
    int r = ty + 16*k;
    size_t g1 = base + (size_t)(i0+r)*LL + j0 + tx;
    uu1[r][tx] = g_uu[g1];
    ah1[k]     = g_ah[g1];
    if (!diag) {
      size_t g2 = base + (size_t)(j0+r)*LL + i0 + tx;
      uu2[r][tx] = g_uu[g2];
      ah2[k]     = g_ah[g2];
    }
  }
  __syncthreads();

  // per-thread column factors in registers
  float aJ=fJ[0][tx], uJ=fJ[1][tx], cJ=fJ[2][tx], gJ=fJ[3][tx];
  float aI=fI[0][tx], uI=fI[1][tx], cI=fI[2][tx], gI=fI[3][tx];
  float sJtx = sJ[tx], sItx = sI[tx];

  float m1[2], m2[2];
  #pragma unroll
  for (int k=0;k<2;k++){
    int r = ty + 16*k;
    // ---- tile1: rows in I, cols in J ----
    {
      float m = mrc(fI, r, aJ, uJ, cJ, gJ);
      m1[k] = m;
      float u12 = uu1[r][tx];
      float u21 = diag ? uu1[tx][r] : uu2[tx][r];
      float grad = ah1[k]*m*fmaf(-0.5f, u12+u21, sI[r] + sJtx);
      float o    = mlp3(wS,    ah1[k], grad, u12);
      float rho  = mlp3(wS+16, ah1[k], grad, u12);
      float ahn  = fminf(fmaxf(o - rho, 0.f), 1.f);
      g_ah[base + (size_t)(i0+r)*LL + j0 + tx] = ahn;
      sq1[r][tx] = ahn*ahn;
    }
    // ---- tile2: rows in J, cols in I ----
    if (!diag) {
      float m = mrc(fJ, r, aI, uI, cI, gI);
      m2[k] = m;
      float u12 = uu2[r][tx];
      float u21 = uu1[tx][r];
      float grad = ah2[k]*m*fmaf(-0.5f, u12+u21, sJ[r] + sItx);
      float o    = mlp3(wS,    ah2[k], grad, u12);
      float rho  = mlp3(wS+16, ah2[k], grad, u12);
      float ahn  = fminf(fmaxf(o - rho, 0.f), 1.f);
      g_ah[base + (size_t)(j0+r)*LL + i0 + tx] = ahn;
      sq2[r][tx] = ahn*ahn;
    }
  }
  __syncthreads();

  // -- phase 3: a, out, next-step partials --
  #pragma unroll
  for (int k=0;k<2;k++){
    int r = ty + 16*k;
    float sT = diag ? sq1[tx][r] : sq2[tx][r];
    float a1 = 0.5f*(sq1[r][tx] + sT)*m1[k];
    __stcs(&out[base + (size_t)(i0+r)*LL + j0 + tx], a1);
    float rs1 = wsum(a1);
    if (tx==0) g_partial[wrbuf][(b*LL + i0 + r)*32 + J] = rs1;
    if (!diag){
      float a2 = 0.5f*(sq2[r][tx] + sq1[tx][r])*m2[k];
      __stcs(&out[base + (size_t)(j0+r)*LL + i0 + tx], a2);
      float rs2 = wsum(a2);
      if (tx==0) g_partial[wrbuf][(b*LL + j0 + r)*32 + I] = rs2;
    }
  }
}

extern "C" void kernel_launch(void* const* d_in, const int* in_sizes, int n_in,
                              void* d_out, int out_size)
{
  // metadata order: u, x, [timesteps], aW1, ab1, aW2, ab2, rW1, rb1, rW2, rb2, lW1, lb1, lW2, lb2
  int off = (n_in >= 15) ? 3 : 2;
  const float* u   = (const float*)d_in[0];
  const float* x   = (const float*)d_in[1];
  const float* aW1 = (const float*)d_in[off+0];
  const float* ab1 = (const float*)d_in[off+1];
  const float* aW2 = (const float*)d_in[off+2];
  const float* ab2 = (const float*)d_in[off+3];
  const float* rW1 = (const float*)d_in[off+4];
  const float* rb1 = (const float*)d_in[off+5];
  const float* rW2 = (const float*)d_in[off+6];
  const float* rb2 = (const float*)d_in[off+7];
  const float* lW1 = (const float*)d_in[off+8];
  const float* lb1 = (const float*)d_in[off+9];
  const float* lW2 = (const float*)d_in[off+10];
  const float* lb2 = (const float*)d_in[off+11];
  float* out = (float*)d_out;

  dim3 grid(528, BB);   // 32*33/2 tile pairs per batch
  init_kernel<<<grid, 256>>>(u, x);
  for (int t = 0; t < NT; ++t) {
    int tm = (t==0) ? 0 : (t-1);   // lambda-MLP weights for step t use index t-1
    step_kernel<<<grid, 512>>>(x,
        aW1 + t*9, ab1 + t*3, aW2 + t*3, ab2 + t,
        rW1 + t*9, rb1 + t*3, rW2 + t*3, rb2 + t,
        lW1 + tm*6, lb1 + tm*3, lW2 + tm*3, lb2 + tm,
        t, out + (size_t)t*BB*LL*LL);
  }
}

// round 7
// speedup vs baseline: 1.1682x; 1.1682x over previous
#include <cuda_runtime.h>
#include <math.h>

#define BB 8
#define LL 1024
#define NT 10
#define SS 2.1972245773362196f   // log(9)

// ---- static device scratch (no allocation allowed) ----
__device__ float g_uu[BB*LL*LL];           // 32 MB
__device__ float g_ah[BB*LL*LL];           // 32 MB
__device__ float g_partial[2][BB*LL*32];   // double-buffered per-row partial sums
__device__ float g_lmbd[2][BB*LL];         // double-buffered lambda state

typedef unsigned long long u64t;
union F2 { u64t u; float2 f; };

__device__ __forceinline__ F2 pk2(float a, float b){ F2 r; r.f.x=a; r.f.y=b; return r; }
__device__ __forceinline__ F2 fma2(F2 a, F2 b, F2 c){
  F2 d; asm("fma.rn.f32x2 %0,%1,%2,%3;" : "=l"(d.u) : "l"(a.u), "l"(b.u), "l"(c.u)); return d;
}
__device__ __forceinline__ F2 relu2(F2 v){ v.f.x=fmaxf(v.f.x,0.f); v.f.y=fmaxf(v.f.y,0.f); return v; }

__device__ __forceinline__ float sigm(float v){ return 1.0f/(1.0f+__expf(-v)); }

__device__ __forceinline__ float wsum(float v){
  #pragma unroll
  for (int o=16;o;o>>=1) v += __shfl_xor_sync(0xffffffffu, v, o);
  return v;
}

__device__ __forceinline__ float mcalc(const float (&fR)[4][32], int r,
                                       const float (&fC)[4][32], int c){
  float bai=fR[0][r], bui=fR[1][r], bci=fR[2][r], bgi=fR[3][r];
  float baj=fC[0][c], buj=fC[1][c], bcj=fC[2][c], bgj=fC[3][c];
  return bai*buj + baj*bui + bci*bgj + bcj*bgi + bui*bgj + buj*bgi;
}

// m from row factors (shared) and column factors (registers)
__device__ __forceinline__ float mrc(const float (&fR)[4][32], int r,
                                     float aC, float uC, float cC, float gC){
  float ai=fR[0][r], ui=fR[1][r], ci=fR[2][r], gi=fR[3][r];
  return ai*uC + aC*ui + ci*gC + cC*gi + ui*gC + uC*gi;
}

// dual 3->3(relu)->1(relu) MLP: .x lane = A-net, .y lane = R-net.
// W[i] holds (wA[i], wR[i]); inputs duplicated across halves.
__device__ __forceinline__ F2 mlpDual(const F2* W, F2 f0, F2 f1, F2 f2){
  F2 h0 = relu2(fma2(W[0],f0, fma2(W[1],f1, fma2(W[2],f2, W[9]))));
  F2 h1 = relu2(fma2(W[3],f0, fma2(W[4],f1, fma2(W[5],f2, W[10]))));
  F2 h2 = relu2(fma2(W[6],f0, fma2(W[7],f1, fma2(W[8],f2, W[11]))));
  return relu2(fma2(W[12],h0, fma2(W[13],h1, fma2(W[14],h2, W[15]))));
}

__device__ __forceinline__ void decode_pair(int p, int &I, int &J){
  I = (int)((sqrtf(8.f*(float)p+1.f)-1.f)*0.5f);
  while ((I+1)*(I+2)/2 <= p) ++I;
  while (I*(I+1)/2 > p) --I;
  J = p - I*(I+1)/2;
}

// ---------------- init: uu, a_hat, rowsum partials of a0 (into buf 0) ----------------
__global__ void __launch_bounds__(256)
init_kernel(const float* __restrict__ u, const float* __restrict__ x)
{
  int b = blockIdx.y;
  int I, J; decode_pair(blockIdx.x, I, J);
  bool diag = (I==J);
  int i0 = I*32, j0 = J*32;
  int tid = threadIdx.x, tx = tid&31, ty = tid>>5;

  __shared__ float sq1[32][33], sq2[32][33];
  __shared__ float fI[4][32], fJ[4][32];

  if (tid < 32) {
    float4 v = ((const float4*)x)[b*LL + i0 + tid];
    fI[0][tid]=v.x; fI[1][tid]=v.y; fI[2][tid]=v.z; fI[3][tid]=v.w;
  } else if (tid < 64) {
    int l = tid-32;
    float4 v = ((const float4*)x)[b*LL + j0 + l];
    fJ[0][l]=v.x; fJ[1][l]=v.y; fJ[2][l]=v.z; fJ[3][l]=v.w;
  }

  const size_t base = (size_t)b*LL*LL;
  #pragma unroll
  for (int k=0;k<4;k++){
    int r = ty + 8*k;
    size_t g1 = base + (size_t)(i0+r)*LL + j0 + tx;
    float uv = u[g1];
    float uu = sigm(2.f*(uv - SS))*uv;
    float ah = sigm(uu)*sigm(2.f*(uu - SS));
    g_uu[g1] = uu; g_ah[g1] = ah;
    sq1[r][tx] = ah*ah;
    if (!diag) {
      size_t g2 = base + (size_t)(j0+r)*LL + i0 + tx;
      float uv2 = u[g2];
      float uu2v = sigm(2.f*(uv2 - SS))*uv2;
      float ah2v = sigm(uu2v)*sigm(2.f*(uu2v - SS));
      g_uu[g2] = uu2v; g_ah[g2] = ah2v;
      sq2[r][tx] = ah2v*ah2v;
    }
  }
  __syncthreads();

  #pragma unroll
  for (int k=0;k<4;k++){
    int r = ty + 8*k;
    float sT = diag ? sq1[tx][r] : sq2[tx][r];
    float a1 = 0.5f*(sq1[r][tx] + sT) * mcalc(fI, r, fJ, tx);
    float rs1 = wsum(a1);
    if (tx==0) g_partial[0][(b*LL + i0 + r)*32 + J] = rs1;
    if (!diag){
      float a2 = 0.5f*(sq2[r][tx] + sq1[tx][r]) * mcalc(fJ, r, fI, tx);
      float rs2 = wsum(a2);
      if (tx==0) g_partial[0][(b*LL + j0 + r)*32 + I] = rs2;
    }
  }
}

// ---------------- main per-timestep kernel (256 thr, 4 rows/thread, fused lambda) ----------------
__global__ void __launch_bounds__(256,3)
step_kernel(const float* __restrict__ x,
  const float* __restrict__ aW1, const float* __restrict__ ab1,
  const float* __restrict__ aW2, const float* __restrict__ ab2,
  const float* __restrict__ rW1, const float* __restrict__ rb1,
  const float* __restrict__ rW2, const float* __restrict__ rb2,
  const float* __restrict__ lW1, const float* __restrict__ lb1,
  const float* __restrict__ lW2, const float* __restrict__ lb2,
  int t, float* __restrict__ out)   // out pre-offset to timestep slice
{
  int b = blockIdx.y;
  int I, J; decode_pair(blockIdx.x, I, J);
  bool diag = (I==J);
  int i0 = I*32, j0 = J*32;
  int tid = threadIdx.x, tx = tid&31, ty = tid>>5;   // ty 0..7

  __shared__ float uu1[32][33], uu2[32][33];
  __shared__ float sq1[32][33], sq2[32][33];
  __shared__ float fI[4][32], fJ[4][32];
  __shared__ float sI[32], sJ[32];
  __shared__ float wS[32];

  const int rdbuf = t & 1, wrbuf = (t+1) & 1;

  // -- setup: per-row factors, weight staging, fused lambda/s --
  if (tid < 32) {
    float4 v = ((const float4*)x)[b*LL + i0 + tid];
    fI[0][tid]=v.x; fI[1][tid]=v.y; fI[2][tid]=v.z; fI[3][tid]=v.w;
  } else if (tid < 64) {
    int l = tid-32;
    float4 v = ((const float4*)x)[b*LL + j0 + l];
    fJ[0][l]=v.x; fJ[1][l]=v.y; fJ[2][l]=v.z; fJ[3][l]=v.w;
  } else if (tid < 128) {
    // fused row work: rowsum -> lg -> lambda update -> s
    int q = tid - 64;
    int row = (q < 32) ? (i0 + q) : (j0 + (q - 32));
    int gi = b*LL + row;
    float rs = 0.f;
    const float4* pp = (const float4*)(&g_partial[rdbuf][(size_t)gi*32]);
    #pragma unroll
    for (int e=0;e<8;e++){ float4 v = pp[e]; rs += (v.x+v.y) + (v.z+v.w); }
    float lg = fmaxf(rs - 1.f, 0.f);
    float lm;
    if (t == 0) {
      lm = lg;                               // W_PEN = 1
    } else {
      float l0 = g_lmbd[rdbuf][gi];
      float h0 = fmaxf(fmaf(__ldg(lW1+0),l0,fmaf(__ldg(lW1+1),lg,__ldg(lb1+0))), 0.f);
      float h1 = fmaxf(fmaf(__ldg(lW1+2),l0,fmaf(__ldg(lW1+3),lg,__ldg(lb1+1))), 0.f);
      float h2 = fmaxf(fmaf(__ldg(lW1+4),l0,fmaf(__ldg(lW1+5),lg,__ldg(lb1+2))), 0.f);
      lm = fmaxf(fmaf(__ldg(lW2+0),h0,fmaf(__ldg(lW2+1),h1,fmaf(__ldg(lW2+2),h2,__ldg(lb2+0)))), 0.f);
    }
    g_lmbd[wrbuf][gi] = lm;                  // duplicate identical writes: deterministic
    float s = lm * sigm(2.f*(rs - 1.f));
    if (q < 32) sI[q] = s; else sJ[q-32] = s;
  } else if (tid < 144) {
    int l = tid-128;
    wS[l] = (l<9) ? aW1[l] : (l<12) ? ab1[l-9] : (l<15) ? aW2[l-12] : ab2[0];
  } else if (tid < 160) {
    int l = tid-144;
    wS[16+l] = (l<9) ? rW1[l] : (l<12) ? rb1[l-9] : (l<15) ? rW2[l-12] : rb2[0];
  }

  // -- load tiles (4 rows per tile per thread) --
  float ah1[4], ah2[4];
  const size_t base = (size_t)b*LL*LL;
  const int tb1 = (i0)*LL + j0 + tx;   // tile1 row-0 element offset (32-bit)
  const int tb2 = (j0)*LL + i0 + tx;   // tile2 row-0 element offset
  #pragma unroll
  for (int k=0;k<4;k++){
    int r = ty + 8*k;
    uu1[r][tx] = g_uu[base + tb1 + r*LL];
    ah1[k]     = g_ah[base + tb1 + r*LL];
    if (!diag) {
      uu2[r][tx] = g_uu[base + tb2 + r*LL];
      ah2[k]     = g_ah[base + tb2 + r*LL];
    }
  }
  __syncthreads();

  // per-thread column factors + dual-packed weights (16 F2 = 32 regs)
  float aJ=fJ[0][tx], uJ=fJ[1][tx], cJ=fJ[2][tx], gJ=fJ[3][tx];
  float aI=fI[0][tx], uI=fI[1][tx], cI=fI[2][tx], gI=fI[3][tx];
  float sJtx = sJ[tx], sItx = sI[tx];
  F2 W[16];
  #pragma unroll
  for (int l=0;l<16;l++) W[l] = pk2(wS[l], wS[16+l]);

  float m1[4], m2[4], q1[4], q2[4];
  #pragma unroll
  for (int k=0;k<4;k++){
    int r = ty + 8*k;
    // ---- tile1: rows in I, cols in J ----
    {
      float m = mrc(fI, r, aJ, uJ, cJ, gJ);
      m1[k] = m;
      float u12 = uu1[r][tx];
      float u21 = diag ? uu1[tx][r] : uu2[tx][r];
      float grad = ah1[k]*m*fmaf(-0.5f, u12+u21, sI[r] + sJtx);
      F2 res = mlpDual(W, pk2(ah1[k],ah1[k]), pk2(grad,grad), pk2(u12,u12));
      float ahn = fminf(fmaxf(res.f.x - res.f.y, 0.f), 1.f);
      g_ah[base + tb1 + r*LL] = ahn;
      float nn = ahn*ahn;
      q1[k] = nn; sq1[r][tx] = nn;
    }
    // ---- tile2: rows in J, cols in I ----
    if (!diag) {
      float m = mrc(fJ, r, aI, uI, cI, gI);
      m2[k] = m;
      float u12 = uu2[r][tx];
      float u21 = uu1[tx][r];
      float grad = ah2[k]*m*fmaf(-0.5f, u12+u21, sJ[r] + sItx);
      F2 res = mlpDual(W, pk2(ah2[k],ah2[k]), pk2(grad,grad), pk2(u12,u12));
      float ahn = fminf(fmaxf(res.f.x - res.f.y, 0.f), 1.f);
      g_ah[base + tb2 + r*LL] = ahn;
      float nn = ahn*ahn;
      q2[k] = nn; sq2[r][tx] = nn;
    }
  }
  __syncthreads();

  // -- phase 3: a, out, next-step partials --
  const bool last = (t == NT-1);
  #pragma unroll
  for (int k=0;k<4;k++){
    int r = ty + 8*k;
    float sT = diag ? sq1[tx][r] : sq2[tx][r];
    float a1 = 0.5f*(q1[k] + sT)*m1[k];
    __stcs(&out[base + tb1 + r*LL], a1);
    if (!last) {
      float rs1 = wsum(a1);
      if (tx==0) g_partial[wrbuf][(b*LL + i0 + r)*32 + J] = rs1;
    }
    if (!diag){
      float a2 = 0.5f*(q2[k] + sq1[tx][r])*m2[k];
      __stcs(&out[base + tb2 + r*LL], a2);
      if (!last) {
        float rs2 = wsum(a2);
        if (tx==0) g_partial[wrbuf][(b*LL + j0 + r)*32 + I] = rs2;
      }
    }
  }
}

extern "C" void kernel_launch(void* const* d_in, const int* in_sizes, int n_in,
                              void* d_out, int out_size)
{
  // metadata order: u, x, [timesteps], aW1, ab1, aW2, ab2, rW1, rb1, rW2, rb2, lW1, lb1, lW2, lb2
  int off = (n_in >= 15) ? 3 : 2;
  const float* u   = (const float*)d_in[0];
  const float* x   = (const float*)d_in[1];
  const float* aW1 = (const float*)d_in[off+0];
  const float* ab1 = (const float*)d_in[off+1];
  const float* aW2 = (const float*)d_in[off+2];
  const float* ab2 = (const float*)d_in[off+3];
  const float* rW1 = (const float*)d_in[off+4];
  const float* rb1 = (const float*)d_in[off+5];
  const float* rW2 = (const float*)d_in[off+6];
  const float* rb2 = (const float*)d_in[off+7];
  const float* lW1 = (const float*)d_in[off+8];
  const float* lb1 = (const float*)d_in[off+9];
  const float* lW2 = (const float*)d_in[off+10];
  const float* lb2 = (const float*)d_in[off+11];
  float* out = (float*)d_out;

  dim3 grid(528, BB);   // 32*33/2 tile pairs per batch
  init_kernel<<<grid, 256>>>(u, x);
  for (int t = 0; t < NT; ++t) {
    int tm = (t==0) ? 0 : (t-1);   // lambda-MLP weights for step t use index t-1
    step_kernel<<<grid, 256>>>(x,
        aW1 + t*9, ab1 + t*3, aW2 + t*3, ab2 + t,
        rW1 + t*9, rb1 + t*3, rW2 + t*3, rb2 + t,
        lW1 + tm*6, lb1 + tm*3, lW2 + tm*3, lb2 + tm,
        t, out + (size_t)t*BB*LL*LL);
  }
}